// round 1
// baseline (speedup 1.0000x reference)
#include <cuda_runtime.h>
#include <cstdint>
#include <cstddef>

#define NB 4
#define P  2048
#define D  64
#define EPS_F     0.1f
#define INV_EPS   10.0f
#define ITERS     50
#define RCHUNKS   16           // row chunks for column pass
#define ROWS_PER_CHUNK (P / RCHUNKS)   // 128
// log(1/2048 + 1e-8) computed in double, rounded to float
#define LOG_MU  (-7.6245985f)
#define LOG_NU  (-7.6245985f)
#define NEG_BIG (-3.0e38f)

// ---------------- static device scratch (no allocations allowed) ----------
__device__ float g_u[NB * P];
__device__ float g_v[NB * P];
__device__ float g_pm[NB * RCHUNKS * P];   // column-pass partial max
__device__ float g_ps[NB * RCHUNKS * P];   // column-pass partial sum
__device__ float g_cp[NB * 1024];          // cost partials (1024 blocks/batch)

// ---------------- init ----------------------------------------------------
__global__ void zero_uv_kernel() {
    int t = blockIdx.x * blockDim.x + threadIdx.x;
    if (t < NB * P) { g_u[t] = 0.0f; g_v[t] = 0.0f; }
}

// ---------------- C = sum_k (x - y)^2 for one batch -----------------------
// 64x64 output tile per block, 16x16 threads, 4x4 micro-tile per thread.
__global__ void c_kernel(const float* __restrict__ x,
                         const float* __restrict__ y,
                         float* __restrict__ C, int n) {
    __shared__ float Xs[64][68];
    __shared__ float Ys[64][68];

    const int tx = threadIdx.x;       // 0..15
    const int ty = threadIdx.y;       // 0..15
    const int tid = ty * 16 + tx;     // 0..255
    const int i0 = blockIdx.y * 64;
    const int j0 = blockIdx.x * 64;

    // cooperative tile load: thread loads 4 float4 of one row
    {
        const int r  = tid >> 2;       // 0..63
        const int c4 = tid & 3;        // 0..3
        const float* xg = x + ((size_t)n * P + i0 + r) * D;
        const float* yg = y + ((size_t)n * P + j0 + r) * D;
#pragma unroll
        for (int q = 0; q < 4; q++) {
            int col = c4 * 16 + q * 4;
            *(float4*)&Xs[r][col] = *(const float4*)(xg + col);
            *(float4*)&Ys[r][col] = *(const float4*)(yg + col);
        }
    }
    __syncthreads();

    float acc[4][4];
#pragma unroll
    for (int a = 0; a < 4; a++)
#pragma unroll
        for (int b = 0; b < 4; b++) acc[a][b] = 0.0f;

#pragma unroll
    for (int k = 0; k < D; k += 4) {
        float4 xa[4], yb[4];
#pragma unroll
        for (int a = 0; a < 4; a++) xa[a] = *(float4*)&Xs[ty * 4 + a][k];
#pragma unroll
        for (int b = 0; b < 4; b++) yb[b] = *(float4*)&Ys[tx * 4 + b][k];
#pragma unroll
        for (int a = 0; a < 4; a++) {
#pragma unroll
            for (int b = 0; b < 4; b++) {
                float d0 = xa[a].x - yb[b].x;
                float d1 = xa[a].y - yb[b].y;
                float d2 = xa[a].z - yb[b].z;
                float d3 = xa[a].w - yb[b].w;
                acc[a][b] = fmaf(d0, d0, acc[a][b]);
                acc[a][b] = fmaf(d1, d1, acc[a][b]);
                acc[a][b] = fmaf(d2, d2, acc[a][b]);
                acc[a][b] = fmaf(d3, d3, acc[a][b]);
            }
        }
    }

    float* Cb = C + (size_t)n * P * P;
#pragma unroll
    for (int a = 0; a < 4; a++) {
        float4 o;
        o.x = acc[a][0]; o.y = acc[a][1]; o.z = acc[a][2]; o.w = acc[a][3];
        *(float4*)&Cb[(size_t)(i0 + ty * 4 + a) * P + j0 + tx * 4] = o;
    }
}

// ---------------- row pass: u_i = eps*(log_mu - LSE_j((v_j - C_ij)/eps)) --
// one warp per row; online LSE per lane over 64 elems (16 float4), warp combine.
__global__ void row_pass(const float* __restrict__ C, int n) {
    const int lane = threadIdx.x & 31;
    const int row  = blockIdx.x * (blockDim.x >> 5) + (threadIdx.x >> 5);
    const float4* Crow = (const float4*)(C + (size_t)n * P * P + (size_t)row * P);
    const float4* V4   = (const float4*)(g_v + n * P);

    float m = NEG_BIG;
    float s = 0.0f;
#pragma unroll 4
    for (int t = lane; t < P / 4; t += 32) {
        float4 c  = Crow[t];
        float4 vv = V4[t];
        float t0 = (vv.x - c.x) * INV_EPS;
        float t1 = (vv.y - c.y) * INV_EPS;
        float t2 = (vv.z - c.z) * INV_EPS;
        float t3 = (vv.w - c.w) * INV_EPS;
        float cm = fmaxf(fmaxf(t0, t1), fmaxf(t2, t3));
        if (cm > m) { s *= __expf(m - cm); m = cm; }
        s += __expf(t0 - m) + __expf(t1 - m) + __expf(t2 - m) + __expf(t3 - m);
    }
    // warp combine of (m, s)
#pragma unroll
    for (int o = 16; o; o >>= 1) {
        float mo = __shfl_xor_sync(0xffffffffu, m, o);
        float so = __shfl_xor_sync(0xffffffffu, s, o);
        float mn = fmaxf(m, mo);
        s = s * __expf(m - mn) + so * __expf(mo - mn);
        m = mn;
    }
    if (lane == 0) {
        float lse = m + __logf(s);
        g_u[n * P + row] = EPS_F * (LOG_MU - lse);
    }
}

// ---------------- column pass (partial): LSE_i over a 128-row chunk -------
// block: 256 threads, one column each; grid (P/256, RCHUNKS)
__global__ void col_pass(const float* __restrict__ C, int n) {
    __shared__ float us[ROWS_PER_CHUNK];
    const int j  = blockIdx.x * 256 + threadIdx.x;
    const int i0 = blockIdx.y * ROWS_PER_CHUNK;
    if (threadIdx.x < ROWS_PER_CHUNK)
        us[threadIdx.x] = g_u[n * P + i0 + threadIdx.x];
    __syncthreads();

    const float* Cc = C + (size_t)n * P * P + (size_t)i0 * P + j;
    float m = NEG_BIG;
    float s = 0.0f;
#pragma unroll 4
    for (int i = 0; i < ROWS_PER_CHUNK; i += 4) {
        float c0 = Cc[0];
        float c1 = Cc[P];
        float c2 = Cc[2 * P];
        float c3 = Cc[3 * P];
        Cc += 4 * (size_t)P;
        float t0 = (us[i + 0] - c0) * INV_EPS;
        float t1 = (us[i + 1] - c1) * INV_EPS;
        float t2 = (us[i + 2] - c2) * INV_EPS;
        float t3 = (us[i + 3] - c3) * INV_EPS;
        float cm = fmaxf(fmaxf(t0, t1), fmaxf(t2, t3));
        if (cm > m) { s *= __expf(m - cm); m = cm; }
        s += __expf(t0 - m) + __expf(t1 - m) + __expf(t2 - m) + __expf(t3 - m);
    }
    g_pm[((size_t)n * RCHUNKS + blockIdx.y) * P + j] = m;
    g_ps[((size_t)n * RCHUNKS + blockIdx.y) * P + j] = s;
}

// ---------------- column combine: v_j from 16 (m,s) partials ---------------
__global__ void col_combine(int n) {
    const int j = blockIdx.x * 256 + threadIdx.x;
    float m = NEG_BIG;
#pragma unroll
    for (int c = 0; c < RCHUNKS; c++)
        m = fmaxf(m, g_pm[((size_t)n * RCHUNKS + c) * P + j]);
    float s = 0.0f;
#pragma unroll
    for (int c = 0; c < RCHUNKS; c++) {
        size_t idx = ((size_t)n * RCHUNKS + c) * P + j;
        s += g_ps[idx] * __expf(g_pm[idx] - m);
    }
    float lse = m + __logf(s);
    g_v[n * P + j] = EPS_F * (LOG_NU - lse);
}

// ---------------- pi = exp((-C+u+v)/eps); cost partial per block -----------
// 4096 blocks x 256 threads; each block covers 4096 contiguous elements
__global__ void pi_cost(const float* __restrict__ C, float* __restrict__ pi) {
    __shared__ float red[256];
    const int b = blockIdx.x;                // 0..4095 (1024 per batch)
    const int n = b >> 10;
    const float4* C4 = (const float4*)C;
    float4* P4 = (float4*)pi;
    const float4* V4 = (const float4*)(g_v + n * P);
    const float* U  = g_u + n * P;
    const size_t base = (size_t)b * 1024;    // in float4 units

    float acc = 0.0f;
#pragma unroll
    for (int p = 0; p < 4; p++) {
        size_t f4 = base + (size_t)p * 256 + threadIdx.x;
        float4 c = C4[f4];
        size_t elem = f4 << 2;
        int i = (int)((elem >> 11) & (P - 1));
        float u = U[i];
        float4 vv = V4[f4 & (P / 4 - 1)];
        float4 pv;
        pv.x = __expf((u + vv.x - c.x) * INV_EPS);
        pv.y = __expf((u + vv.y - c.y) * INV_EPS);
        pv.z = __expf((u + vv.z - c.z) * INV_EPS);
        pv.w = __expf((u + vv.w - c.w) * INV_EPS);
        P4[f4] = pv;
        acc += pv.x * c.x + pv.y * c.y + pv.z * c.z + pv.w * c.w;
    }
    red[threadIdx.x] = acc;
    __syncthreads();
#pragma unroll
    for (int o = 128; o; o >>= 1) {
        if (threadIdx.x < o) red[threadIdx.x] += red[threadIdx.x + o];
        __syncthreads();
    }
    if (threadIdx.x == 0) g_cp[b] = red[0];
}

// ---------------- deterministic cost combine -------------------------------
__global__ void cost_combine(float* __restrict__ cost) {
    __shared__ float red[256];
    const int n = blockIdx.x;
    float a = 0.0f;
#pragma unroll
    for (int q = 0; q < 4; q++)
        a += g_cp[n * 1024 + q * 256 + threadIdx.x];
    red[threadIdx.x] = a;
    __syncthreads();
#pragma unroll
    for (int o = 128; o; o >>= 1) {
        if (threadIdx.x < o) red[threadIdx.x] += red[threadIdx.x + o];
        __syncthreads();
    }
    if (threadIdx.x == 0) cost[n] = red[0];
}

// ---------------- launch ----------------------------------------------------
extern "C" void kernel_launch(void* const* d_in, const int* in_sizes, int n_in,
                              void* d_out, int out_size) {
    const float* x = (const float*)d_in[0];
    const float* y = (const float*)d_in[1];
    float* out  = (float*)d_out;
    float* cost = out;                              // 4 floats
    float* pi   = out + NB;                         // NB*P*P
    float* C    = out + NB + (size_t)NB * P * P;    // NB*P*P

    zero_uv_kernel<<<32, 256>>>();

    for (int n = 0; n < NB; n++) {
        // compute this batch's C directly into the output buffer
        c_kernel<<<dim3(P / 64, P / 64), dim3(16, 16)>>>(x, y, C, n);
        // 50 Sinkhorn iterations on this batch while its C slice is L2-hot
        for (int it = 0; it < ITERS; it++) {
            row_pass<<<P / 8, 256>>>(C, n);
            col_pass<<<dim3(P / 256, RCHUNKS), 256>>>(C, n);
            col_combine<<<P / 256, 256>>>(n);
        }
    }

    pi_cost<<<NB * 1024, 256>>>(C, pi);
    cost_combine<<<NB, 256>>>(cost);
}

// round 2
// speedup vs baseline: 2.2078x; 2.2078x over previous
#include <cuda_runtime.h>
#include <cstdint>
#include <cstddef>

#define NB 4
#define P  2048
#define D  64
#define ITERS     50
#define RCHUNKS   16
#define ROWS_PER_CHUNK (P / RCHUNKS)   // 128
// 10 * log2(e)
#define K2E 14.4269504089f
// ln(1/2048 + 1e-8) / ln(2)
#define LOG_MU2 (-10.99997045f)
#define LOG_NU2 (-10.99997045f)
#define NEG_BIG (-3.0e38f)
#define LN2_OVER10 0.06931471805599453f

__device__ __forceinline__ float ex2f(float x) {
    float r; asm("ex2.approx.f32 %0, %1;" : "=f"(r) : "f"(x)); return r;
}
__device__ __forceinline__ float lg2f(float x) {
    float r; asm("lg2.approx.f32 %0, %1;" : "=f"(r) : "f"(x)); return r;
}

// ---------------- static device scratch -----------------------------------
__device__ float g_us2[NB * P];              // u * 10*log2e
__device__ float g_vs2[NB * P];              // v * 10*log2e
__device__ float g_pm2[NB * RCHUNKS * P];    // column partial max (base-2)
__device__ float g_ps2[NB * RCHUNKS * P];    // column partial sum
__device__ float g_cp[NB * 1024];            // cost partials

// ---------------- init: v = 0 ----------------------------------------------
__global__ void zero_vs2() {
    int t = blockIdx.x * 256 + threadIdx.x;
    if (t < NB * P) g_vs2[t] = 0.0f;
}

// ---------------- C = sum_k (x - y)^2, all batches --------------------------
__global__ __launch_bounds__(256) void c_kernel(const float* __restrict__ x,
                                                const float* __restrict__ y,
                                                float* __restrict__ C) {
    __shared__ float Xs[64][68];
    __shared__ float Ys[64][68];
    const int tx = threadIdx.x, ty = threadIdx.y;
    const int tid = ty * 16 + tx;
    const int n  = blockIdx.z;
    const int i0 = blockIdx.y * 64;
    const int j0 = blockIdx.x * 64;

    {
        const int r  = tid >> 2;
        const int c4 = tid & 3;
        const float* xg = x + ((size_t)n * P + i0 + r) * D;
        const float* yg = y + ((size_t)n * P + j0 + r) * D;
#pragma unroll
        for (int q = 0; q < 4; q++) {
            int col = c4 * 16 + q * 4;
            *(float4*)&Xs[r][col] = *(const float4*)(xg + col);
            *(float4*)&Ys[r][col] = *(const float4*)(yg + col);
        }
    }
    __syncthreads();

    float acc[4][4];
#pragma unroll
    for (int a = 0; a < 4; a++)
#pragma unroll
        for (int b = 0; b < 4; b++) acc[a][b] = 0.0f;

#pragma unroll
    for (int k = 0; k < D; k += 4) {
        float4 xa[4], yb[4];
#pragma unroll
        for (int a = 0; a < 4; a++) xa[a] = *(float4*)&Xs[ty * 4 + a][k];
#pragma unroll
        for (int b = 0; b < 4; b++) yb[b] = *(float4*)&Ys[tx * 4 + b][k];
#pragma unroll
        for (int a = 0; a < 4; a++)
#pragma unroll
            for (int b = 0; b < 4; b++) {
                float d0 = xa[a].x - yb[b].x;
                float d1 = xa[a].y - yb[b].y;
                float d2 = xa[a].z - yb[b].z;
                float d3 = xa[a].w - yb[b].w;
                acc[a][b] = fmaf(d0, d0, acc[a][b]);
                acc[a][b] = fmaf(d1, d1, acc[a][b]);
                acc[a][b] = fmaf(d2, d2, acc[a][b]);
                acc[a][b] = fmaf(d3, d3, acc[a][b]);
            }
    }

    float* Cb = C + (size_t)n * P * P;
#pragma unroll
    for (int a = 0; a < 4; a++) {
        float4 o;
        o.x = acc[a][0]; o.y = acc[a][1]; o.z = acc[a][2]; o.w = acc[a][3];
        *(float4*)&Cb[(size_t)(i0 + ty * 4 + a) * P + j0 + tx * 4] = o;
    }
}

// ---------------- K1: row pass, all batches ---------------------------------
// us2_i = LOG_MU2 - log2( sum_j 2^(vs2_j - C_ij*K2E) )
// 8 warps/block = 8 rows/block; grid = NB*P/8 = 1024 blocks
__global__ __launch_bounds__(256) void row_k1(const float* __restrict__ C) {
    __shared__ float vs[P];
    const int lane = threadIdx.x & 31;
    const int warp = threadIdx.x >> 5;
    const int row  = blockIdx.x * 8 + warp;      // global row 0..8191
    const int n    = row >> 11;

    // load this batch's vs2 into smem (float4, coalesced)
    {
        const float4* src = (const float4*)(g_vs2 + (n << 11));
        float4* dst = (float4*)vs;
#pragma unroll
        for (int t = threadIdx.x; t < P / 4; t += 256) dst[t] = src[t];
    }
    __syncthreads();

    const float4* Crow = (const float4*)(C + (size_t)row * P);
    const float4* V4   = (const float4*)vs;

    float m = NEG_BIG, s = 0.0f;
#pragma unroll 4
    for (int t = lane; t < P / 4; t += 32) {
        float4 c  = Crow[t];
        float4 vv = V4[t];
        float b0 = fmaf(c.x, -K2E, vv.x);
        float b1 = fmaf(c.y, -K2E, vv.y);
        float b2 = fmaf(c.z, -K2E, vv.z);
        float b3 = fmaf(c.w, -K2E, vv.w);
        float cm = fmaxf(fmaxf(b0, b1), fmaxf(b2, b3));
        if (cm > m) { s *= ex2f(m - cm); m = cm; }
        s += ex2f(b0 - m) + ex2f(b1 - m) + ex2f(b2 - m) + ex2f(b3 - m);
    }
#pragma unroll
    for (int o = 16; o; o >>= 1) {
        float mo = __shfl_xor_sync(0xffffffffu, m, o);
        float so = __shfl_xor_sync(0xffffffffu, s, o);
        float mn = fmaxf(m, mo);
        s = s * ex2f(m - mn) + so * ex2f(mo - mn);
        m = mn;
    }
    if (lane == 0) g_us2[row] = LOG_MU2 - (m + lg2f(s));
}

// ---------------- K2: column partials, all batches ---------------------------
// grid (P/256, RCHUNKS, NB), 256 threads, thread = one column
__global__ __launch_bounds__(256) void col_k2(const float* __restrict__ C) {
    __shared__ float us[ROWS_PER_CHUNK];
    const int n  = blockIdx.z;
    const int j  = blockIdx.x * 256 + threadIdx.x;
    const int i0 = blockIdx.y * ROWS_PER_CHUNK;
    if (threadIdx.x < ROWS_PER_CHUNK)
        us[threadIdx.x] = g_us2[(n << 11) + i0 + threadIdx.x];
    __syncthreads();

    const float* Cc = C + (size_t)n * P * P + (size_t)i0 * P + j;
    float m = NEG_BIG, s = 0.0f;
#pragma unroll 4
    for (int i = 0; i < ROWS_PER_CHUNK; i += 4) {
        float c0 = Cc[0];
        float c1 = Cc[P];
        float c2 = Cc[2 * P];
        float c3 = Cc[3 * P];
        Cc += 4 * (size_t)P;
        float b0 = fmaf(c0, -K2E, us[i + 0]);
        float b1 = fmaf(c1, -K2E, us[i + 1]);
        float b2 = fmaf(c2, -K2E, us[i + 2]);
        float b3 = fmaf(c3, -K2E, us[i + 3]);
        float cm = fmaxf(fmaxf(b0, b1), fmaxf(b2, b3));
        if (cm > m) { s *= ex2f(m - cm); m = cm; }
        s += ex2f(b0 - m) + ex2f(b1 - m) + ex2f(b2 - m) + ex2f(b3 - m);
    }
    const size_t o = ((size_t)n * RCHUNKS + blockIdx.y) * P + j;
    g_pm2[o] = m;
    g_ps2[o] = s;
}

// ---------------- K3: column combine -> vs2, all batches ---------------------
__global__ __launch_bounds__(256) void col_k3() {
    const int jg = blockIdx.x * 256 + threadIdx.x;  // 0..8191
    const int n  = jg >> 11;
    const int j  = jg & (P - 1);
    float m = NEG_BIG;
#pragma unroll
    for (int c = 0; c < RCHUNKS; c++)
        m = fmaxf(m, g_pm2[((size_t)n * RCHUNKS + c) * P + j]);
    float s = 0.0f;
#pragma unroll
    for (int c = 0; c < RCHUNKS; c++) {
        size_t idx = ((size_t)n * RCHUNKS + c) * P + j;
        s += g_ps2[idx] * ex2f(g_pm2[idx] - m);
    }
    g_vs2[jg] = LOG_NU2 - (m + lg2f(s));
}

// ---------------- pi = 2^(us2 + vs2 - C*K2E); cost partials ------------------
__global__ __launch_bounds__(256) void pi_cost(const float* __restrict__ C,
                                               float* __restrict__ pi) {
    __shared__ float red[256];
    const int b = blockIdx.x;               // 0..4095
    const int n = b >> 10;
    const float4* C4 = (const float4*)C;
    float4* P4 = (float4*)pi;
    const float4* V4 = (const float4*)(g_vs2 + (n << 11));
    const size_t base = (size_t)b * 1024;   // float4 units

    float acc = 0.0f;
#pragma unroll
    for (int p = 0; p < 4; p++) {
        size_t f4 = base + (size_t)p * 256 + threadIdx.x;
        float4 c = C4[f4];
        int ig = (int)(f4 >> 9);            // global row 0..8191
        float u = g_us2[ig];
        float4 vv = V4[f4 & (P / 4 - 1)];
        float4 pv;
        pv.x = ex2f(fmaf(c.x, -K2E, u + vv.x));
        pv.y = ex2f(fmaf(c.y, -K2E, u + vv.y));
        pv.z = ex2f(fmaf(c.z, -K2E, u + vv.z));
        pv.w = ex2f(fmaf(c.w, -K2E, u + vv.w));
        P4[f4] = pv;
        acc += pv.x * c.x + pv.y * c.y + pv.z * c.z + pv.w * c.w;
    }
    red[threadIdx.x] = acc;
    __syncthreads();
#pragma unroll
    for (int o = 128; o; o >>= 1) {
        if (threadIdx.x < o) red[threadIdx.x] += red[threadIdx.x + o];
        __syncthreads();
    }
    if (threadIdx.x == 0) g_cp[b] = red[0];
}

__global__ __launch_bounds__(256) void cost_combine(float* __restrict__ cost) {
    __shared__ float red[256];
    const int n = blockIdx.x;
    float a = 0.0f;
#pragma unroll
    for (int q = 0; q < 4; q++)
        a += g_cp[n * 1024 + q * 256 + threadIdx.x];
    red[threadIdx.x] = a;
    __syncthreads();
#pragma unroll
    for (int o = 128; o; o >>= 1) {
        if (threadIdx.x < o) red[threadIdx.x] += red[threadIdx.x + o];
        __syncthreads();
    }
    if (threadIdx.x == 0) cost[n] = red[0];
}

// ---------------- launch ------------------------------------------------------
extern "C" void kernel_launch(void* const* d_in, const int* in_sizes, int n_in,
                              void* d_out, int out_size) {
    const float* x = (const float*)d_in[0];
    const float* y = (const float*)d_in[1];
    float* out  = (float*)d_out;
    float* cost = out;
    float* pi   = out + NB;
    float* C    = out + NB + (size_t)NB * P * P;

    zero_vs2<<<32, 256>>>();
    c_kernel<<<dim3(P / 64, P / 64, NB), dim3(16, 16)>>>(x, y, C);

    for (int it = 0; it < ITERS; it++) {
        row_k1<<<NB * P / 8, 256>>>(C);
        col_k2<<<dim3(P / 256, RCHUNKS, NB), 256>>>(C);
        col_k3<<<NB * P / 256, 256>>>();
    }

    pi_cost<<<NB * 1024, 256>>>(C, pi);
    cost_combine<<<NB, 256>>>(cost);
}

// round 3
// speedup vs baseline: 2.2475x; 1.0180x over previous
#include <cuda_runtime.h>
#include <cstdint>
#include <cstddef>

#define NB 4
#define P  2048
#define D  64
#define ITERS     50
#define RCHUNKS   32
#define ROWS_PER_CHUNK (P / RCHUNKS)   // 64
#define JBLKS     (P / 256)            // 8
// 10 * log2(e)
#define K2E 14.4269504089f
// log2(1/2048 + 1e-8)
#define LOG_MU2 (-10.99997045f)
#define LOG_NU2 (-10.99997045f)
#define NEG_BIG (-3.0e38f)

__device__ __forceinline__ float ex2f(float x) {
    float r; asm("ex2.approx.f32 %0, %1;" : "=f"(r) : "f"(x)); return r;
}
__device__ __forceinline__ float lg2f(float x) {
    float r; asm("lg2.approx.f32 %0, %1;" : "=f"(r) : "f"(x)); return r;
}

// ---------------- static device scratch -----------------------------------
__device__ float g_us2[NB * P];
__device__ float g_vs2[NB * P];
__device__ float g_xx[NB * P];
__device__ float g_yy[NB * P];
__device__ float g_pm2[NB * RCHUNKS * P];
__device__ float g_ps2[NB * RCHUNKS * P];
__device__ float g_cp[NB * 1024];
__device__ unsigned g_ticket[NB * JBLKS];

// ---------------- init -------------------------------------------------------
__global__ void init_kernel() {
    int t = blockIdx.x * 256 + threadIdx.x;
    if (t < NB * P) g_vs2[t] = 0.0f;
    if (t < NB * JBLKS) g_ticket[t] = 0u;
}

// ---------------- squared norms ----------------------------------------------
__global__ __launch_bounds__(256) void norms_kernel(const float* __restrict__ x,
                                                    const float* __restrict__ y) {
    const int r = blockIdx.x * 256 + threadIdx.x;   // 0..NB*P-1
    const float4* xr = (const float4*)(x + (size_t)r * D);
    const float4* yr = (const float4*)(y + (size_t)r * D);
    float ax = 0.0f, ay = 0.0f;
#pragma unroll
    for (int t = 0; t < D / 4; t++) {
        float4 a = xr[t], b = yr[t];
        ax = fmaf(a.x, a.x, ax); ax = fmaf(a.y, a.y, ax);
        ax = fmaf(a.z, a.z, ax); ax = fmaf(a.w, a.w, ax);
        ay = fmaf(b.x, b.x, ay); ay = fmaf(b.y, b.y, ay);
        ay = fmaf(b.z, b.z, ay); ay = fmaf(b.w, b.w, ay);
    }
    g_xx[r] = ax;
    g_yy[r] = ay;
}

// ---------------- C = xx_i + yy_j - 2*x.y, all batches -------------------------
__global__ __launch_bounds__(256) void c_kernel(const float* __restrict__ x,
                                                const float* __restrict__ y,
                                                float* __restrict__ C) {
    __shared__ float Xs[64][68];
    __shared__ float Ys[64][68];
    const int tx = threadIdx.x, ty = threadIdx.y;
    const int tid = ty * 16 + tx;
    const int n  = blockIdx.z;
    const int i0 = blockIdx.y * 64;
    const int j0 = blockIdx.x * 64;

    {
        const int r  = tid >> 2;
        const int c4 = tid & 3;
        const float* xg = x + ((size_t)n * P + i0 + r) * D;
        const float* yg = y + ((size_t)n * P + j0 + r) * D;
#pragma unroll
        for (int q = 0; q < 4; q++) {
            int col = c4 * 16 + q * 4;
            *(float4*)&Xs[r][col] = *(const float4*)(xg + col);
            *(float4*)&Ys[r][col] = *(const float4*)(yg + col);
        }
    }
    __syncthreads();

    float acc[4][4];
#pragma unroll
    for (int a = 0; a < 4; a++)
#pragma unroll
        for (int b = 0; b < 4; b++) acc[a][b] = 0.0f;

#pragma unroll
    for (int k = 0; k < D; k += 4) {
        float4 xa[4], yb[4];
#pragma unroll
        for (int a = 0; a < 4; a++) xa[a] = *(float4*)&Xs[ty * 4 + a][k];
#pragma unroll
        for (int b = 0; b < 4; b++) yb[b] = *(float4*)&Ys[tx * 4 + b][k];
#pragma unroll
        for (int a = 0; a < 4; a++)
#pragma unroll
            for (int b = 0; b < 4; b++) {
                acc[a][b] = fmaf(xa[a].x, yb[b].x, acc[a][b]);
                acc[a][b] = fmaf(xa[a].y, yb[b].y, acc[a][b]);
                acc[a][b] = fmaf(xa[a].z, yb[b].z, acc[a][b]);
                acc[a][b] = fmaf(xa[a].w, yb[b].w, acc[a][b]);
            }
    }

    float yyv[4];
#pragma unroll
    for (int b = 0; b < 4; b++) yyv[b] = g_yy[(n << 11) + j0 + tx * 4 + b];

    float* Cb = C + (size_t)n * P * P;
#pragma unroll
    for (int a = 0; a < 4; a++) {
        float xxv = g_xx[(n << 11) + i0 + ty * 4 + a];
        float4 o;
        o.x = fmaf(-2.0f, acc[a][0], xxv + yyv[0]);
        o.y = fmaf(-2.0f, acc[a][1], xxv + yyv[1]);
        o.z = fmaf(-2.0f, acc[a][2], xxv + yyv[2]);
        o.w = fmaf(-2.0f, acc[a][3], xxv + yyv[3]);
        *(float4*)&Cb[(size_t)(i0 + ty * 4 + a) * P + j0 + tx * 4] = o;
    }
}

// ---------------- LSE group helper (branchless, dual-accumulator) -------------
__device__ __forceinline__ void lse_group(float4 c, float vx, float vy, float vz, float vw,
                                          float& m, float& s) {
    float b0 = fmaf(c.x, -K2E, vx);
    float b1 = fmaf(c.y, -K2E, vy);
    float b2 = fmaf(c.z, -K2E, vz);
    float b3 = fmaf(c.w, -K2E, vw);
    float cm = fmaxf(fmaxf(b0, b1), fmaxf(b2, b3));
    float mn = fmaxf(m, cm);
    s = fmaf(s, ex2f(m - mn),
             ex2f(b0 - mn) + ex2f(b1 - mn) + ex2f(b2 - mn) + ex2f(b3 - mn));
    m = mn;
}

// ---------------- K1: row pass (forward sweep) ---------------------------------
__global__ __launch_bounds__(256) void row_k1(const float* __restrict__ C) {
    __shared__ float vs[P];
    const int lane = threadIdx.x & 31;
    const int warp = threadIdx.x >> 5;
    const int row  = blockIdx.x * 8 + warp;      // 0..8191
    const int n    = row >> 11;

    {
        const float4* src = (const float4*)(g_vs2 + (n << 11));
        float4* dst = (float4*)vs;
#pragma unroll
        for (int t = threadIdx.x; t < P / 4; t += 256) dst[t] = src[t];
    }
    __syncthreads();

    const float4* Crow = (const float4*)(C + (size_t)row * P);
    const float4* V4   = (const float4*)vs;

    float m0 = NEG_BIG, s0 = 0.0f, m1 = NEG_BIG, s1 = 0.0f;
#pragma unroll
    for (int it = 0; it < 4; it++) {
        const int t = lane + it * 128;
        float4 c0 = Crow[t];
        float4 c1 = Crow[t + 32];
        float4 c2 = Crow[t + 64];
        float4 c3 = Crow[t + 96];
        float4 v0 = V4[t];
        float4 v1 = V4[t + 32];
        float4 v2 = V4[t + 64];
        float4 v3 = V4[t + 96];
        lse_group(c0, v0.x, v0.y, v0.z, v0.w, m0, s0);
        lse_group(c1, v1.x, v1.y, v1.z, v1.w, m1, s1);
        lse_group(c2, v2.x, v2.y, v2.z, v2.w, m0, s0);
        lse_group(c3, v3.x, v3.y, v3.z, v3.w, m1, s1);
    }
    // merge dual accumulators
    float m = fmaxf(m0, m1);
    float s = s0 * ex2f(m0 - m) + s1 * ex2f(m1 - m);
#pragma unroll
    for (int o = 16; o; o >>= 1) {
        float mo = __shfl_xor_sync(0xffffffffu, m, o);
        float so = __shfl_xor_sync(0xffffffffu, s, o);
        float mn = fmaxf(m, mo);
        s = s * ex2f(m - mn) + so * ex2f(mo - mn);
        m = mn;
    }
    if (lane == 0) g_us2[row] = LOG_MU2 - (m + lg2f(s));
}

// ---------------- K2: column pass, reversed sweep, fused combine ----------------
__global__ __launch_bounds__(256) void col_k2(const float* __restrict__ C) {
    __shared__ float us[ROWS_PER_CHUNK];
    __shared__ unsigned last;
    const int rev   = (int)gridDim.x - 1 - (int)blockIdx.x;   // serpentine
    const int jblk  = rev & (JBLKS - 1);
    const int chunk = (rev >> 3) & (RCHUNKS - 1);
    const int n     = rev >> 8;
    const int j     = jblk * 256 + threadIdx.x;
    const int i0    = chunk * ROWS_PER_CHUNK;

    if (threadIdx.x < ROWS_PER_CHUNK)
        us[threadIdx.x] = g_us2[(n << 11) + i0 + threadIdx.x];
    __syncthreads();

    const float* Cc = C + (size_t)n * P * P + (size_t)i0 * P + j;
    float m0 = NEG_BIG, s0 = 0.0f, m1 = NEG_BIG, s1 = 0.0f;
#pragma unroll
    for (int i = 0; i < ROWS_PER_CHUNK; i += 8) {
        float c0 = Cc[0];
        float c1 = Cc[(size_t)P];
        float c2 = Cc[2 * (size_t)P];
        float c3 = Cc[3 * (size_t)P];
        float c4 = Cc[4 * (size_t)P];
        float c5 = Cc[5 * (size_t)P];
        float c6 = Cc[6 * (size_t)P];
        float c7 = Cc[7 * (size_t)P];
        Cc += 8 * (size_t)P;
        float4 ca = {c0, c1, c2, c3};
        float4 cb = {c4, c5, c6, c7};
        lse_group(ca, us[i], us[i + 1], us[i + 2], us[i + 3], m0, s0);
        lse_group(cb, us[i + 4], us[i + 5], us[i + 6], us[i + 7], m1, s1);
    }
    float m = fmaxf(m0, m1);
    float s = s0 * ex2f(m0 - m) + s1 * ex2f(m1 - m);

    const size_t po = ((size_t)n * RCHUNKS + chunk) * P + j;
    g_pm2[po] = m;
    g_ps2[po] = s;

    // ticket: last block for (n, jblk) combines all RCHUNKS partials
    __threadfence();
    if (threadIdx.x == 0)
        last = atomicAdd(&g_ticket[n * JBLKS + jblk], 1u);
    __syncthreads();
    if (last == RCHUNKS - 1) {
        __threadfence();
        float mm = NEG_BIG;
#pragma unroll
        for (int c = 0; c < RCHUNKS; c++)
            mm = fmaxf(mm, __ldcg(&g_pm2[((size_t)n * RCHUNKS + c) * P + j]));
        float ss = 0.0f;
#pragma unroll
        for (int c = 0; c < RCHUNKS; c++) {
            size_t idx = ((size_t)n * RCHUNKS + c) * P + j;
            ss += __ldcg(&g_ps2[idx]) * ex2f(__ldcg(&g_pm2[idx]) - mm);
        }
        g_vs2[(n << 11) + j] = LOG_NU2 - (mm + lg2f(ss));
        if (threadIdx.x == 0) g_ticket[n * JBLKS + jblk] = 0u;
    }
}

// ---------------- pi + cost partials --------------------------------------------
__global__ __launch_bounds__(256) void pi_cost(const float* __restrict__ C,
                                               float* __restrict__ pi) {
    __shared__ float red[256];
    const int b = blockIdx.x;               // 0..4095
    const int n = b >> 10;
    const float4* C4 = (const float4*)C;
    float4* P4 = (float4*)pi;
    const float4* V4 = (const float4*)(g_vs2 + (n << 11));
    const size_t base = (size_t)b * 1024;

    float acc = 0.0f;
#pragma unroll
    for (int p = 0; p < 4; p++) {
        size_t f4 = base + (size_t)p * 256 + threadIdx.x;
        float4 c = C4[f4];
        int ig = (int)(f4 >> 9);
        float u = g_us2[ig];
        float4 vv = V4[f4 & (P / 4 - 1)];
        float4 pv;
        pv.x = ex2f(fmaf(c.x, -K2E, u + vv.x));
        pv.y = ex2f(fmaf(c.y, -K2E, u + vv.y));
        pv.z = ex2f(fmaf(c.z, -K2E, u + vv.z));
        pv.w = ex2f(fmaf(c.w, -K2E, u + vv.w));
        P4[f4] = pv;
        acc += pv.x * c.x + pv.y * c.y + pv.z * c.z + pv.w * c.w;
    }
    red[threadIdx.x] = acc;
    __syncthreads();
#pragma unroll
    for (int o = 128; o; o >>= 1) {
        if (threadIdx.x < o) red[threadIdx.x] += red[threadIdx.x + o];
        __syncthreads();
    }
    if (threadIdx.x == 0) g_cp[b] = red[0];
}

__global__ __launch_bounds__(256) void cost_combine(float* __restrict__ cost) {
    __shared__ float red[256];
    const int n = blockIdx.x;
    float a = 0.0f;
#pragma unroll
    for (int q = 0; q < 4; q++)
        a += g_cp[n * 1024 + q * 256 + threadIdx.x];
    red[threadIdx.x] = a;
    __syncthreads();
#pragma unroll
    for (int o = 128; o; o >>= 1) {
        if (threadIdx.x < o) red[threadIdx.x] += red[threadIdx.x + o];
        __syncthreads();
    }
    if (threadIdx.x == 0) cost[n] = red[0];
}

// ---------------- launch ----------------------------------------------------------
extern "C" void kernel_launch(void* const* d_in, const int* in_sizes, int n_in,
                              void* d_out, int out_size) {
    const float* x = (const float*)d_in[0];
    const float* y = (const float*)d_in[1];
    float* out  = (float*)d_out;
    float* cost = out;
    float* pi   = out + NB;
    float* C    = out + NB + (size_t)NB * P * P;

    init_kernel<<<32, 256>>>();
    norms_kernel<<<NB * P / 256, 256>>>(x, y);
    c_kernel<<<dim3(P / 64, P / 64, NB), dim3(16, 16)>>>(x, y, C);

    for (int it = 0; it < ITERS; it++) {
        row_k1<<<NB * P / 8, 256>>>(C);
        col_k2<<<NB * RCHUNKS * JBLKS, 256>>>(C);
    }

    pi_cost<<<NB * 1024, 256>>>(C, pi);
    cost_combine<<<NB, 256>>>(cost);
}